// round 15
// baseline (speedup 1.0000x reference)
#include <cuda_runtime.h>
#include <cuda_fp16.h>
#include <cstdint>
#include <math.h>

#define Hh 96
#define Ww 96
#define HW 9216
#define Fch 96
#define CIN 8
#define Lk 5
#define Sg 10
#define Bg 4
#define FH3 288          // 3*F
#define K1 480           // L*F
#define KPAD 512         // row STRIDE of k-major operands (pad cols never read)
#define CH 112           // packed input channels: 8 x | 96 h | 8 zero
#define STEP_ELEMS (Bg*Fch*HW)   // 3,538,944

// ---- scratch (device globals) ----
__device__ __align__(16) __half g_i2h[(size_t)Sg*Bg*FH3*HW];  // 212 MB (once), fp16
__device__ __align__(16) __half g_whi[(size_t)Bg*HW*KPAD];    // warped^T hi [b][p][k]
__device__ __align__(16) __half g_Ahi[(size_t)FH3*KPAD];      // w_ret hi [m][k]
// fconv inputs: per-step slots [Sg][Bg][p][112] (hi only)
__device__ __align__(16) __half g_inhi[(size_t)Sg*Bg*HW*CH];
__device__ __align__(16) __half g_wfhi[7*25*32*16];           // [chunk][tap][oc][16]
// f (1-term) [b][p][32]
__device__ __align__(16) __half g_fhi[(size_t)Bg*HW*32];
// flows weights [chunk2][tap25][oc32][16] (oc>=10 zero)
__device__ __align__(16) __half g_w2hi[2*25*32*16];
// i2h weights [ocg3][tap9][oc96][8] (1-term)
__device__ __align__(16) __half g_w3hi[3*9*96*8];

__device__ __forceinline__ float leaky(float v){ return v > 0.f ? v : 0.2f*v; }
__device__ __forceinline__ float sigm(float v){ return 1.f/(1.f + expf(-v)); }

__device__ __forceinline__ uint32_t smem_u32(const void* p){
    uint32_t a;
    asm("{ .reg .u64 t; cvta.to.shared.u64 t, %1; cvt.u32.u64 %0, t; }" : "=r"(a) : "l"(p));
    return a;
}
__device__ __forceinline__ void ldm_x4(uint32_t* r, uint32_t addr){
    asm volatile("ldmatrix.sync.aligned.m8n8.x4.shared.b16 {%0,%1,%2,%3}, [%4];"
        : "=r"(r[0]), "=r"(r[1]), "=r"(r[2]), "=r"(r[3]) : "r"(addr));
}
__device__ __forceinline__ void ldm_x2(uint32_t* r, uint32_t addr){
    asm volatile("ldmatrix.sync.aligned.m8n8.x2.shared.b16 {%0,%1}, [%2];"
        : "=r"(r[0]), "=r"(r[1]) : "r"(addr));
}
#define MMA_F16(c, a, b) \
    asm volatile("mma.sync.aligned.m16n8k16.row.col.f32.f16.f16.f32 " \
        "{%0,%1,%2,%3}, {%4,%5,%6,%7}, {%8,%9}, {%0,%1,%2,%3};" \
        : "+f"((c)[0]), "+f"((c)[1]), "+f"((c)[2]), "+f"((c)[3]) \
        : "r"((a)[0]), "r"((a)[1]), "r"((a)[2]), "r"((a)[3]), \
          "r"((b)[0]), "r"((b)[1]))
#define MMA_F16_K8(c, a, b) \
    asm volatile("mma.sync.aligned.m16n8k8.row.col.f32.f16.f16.f32 " \
        "{%0,%1,%2,%3}, {%4,%5}, {%6}, {%0,%1,%2,%3};" \
        : "+f"((c)[0]), "+f"((c)[1]), "+f"((c)[2]), "+f"((c)[3]) \
        : "r"((a)[0]), "r"((a)[1]), "r"(b))
#define CPA16(sm, gp) asm volatile("cp.async.ca.shared.global [%0], [%1], 16;" :: "r"(sm), "l"(gp))
#define CPA_COMMIT()  asm volatile("cp.async.commit_group;" ::: "memory")

__device__ __forceinline__ uint32_t pack2(float v0, float v1){
    __half2 hp = __halves2half2(__float2half(v0), __float2half(v1));
    return *reinterpret_cast<uint32_t*>(&hp);
}

// ============================================================
// k_prepX (once): pack x channels (hi) for ALL step slots, zero pad,
// slot-0 h channels from h0.
// ============================================================
__global__ void k_prepX(const float* __restrict__ inputs, const float* __restrict__ h0){
    int idx = blockIdx.x*blockDim.x + threadIdx.x;
    if (idx >= Sg*Bg*HW) return;
    int p = idx % HW, b = (idx/HW) % Bg, t = idx/(HW*Bg);
    size_t base = ((size_t)(t*Bg + b)*HW + p)*CH;
    const float* xp = inputs + ((size_t)(t*Bg + b)*CIN)*HW + p;
    uint32_t hw[4];
    #pragma unroll
    for (int q = 0; q < 4; q++)
        hw[q] = pack2(xp[(size_t)(2*q)*HW], xp[(size_t)(2*q+1)*HW]);
    *reinterpret_cast<uint4*>(g_inhi + base) = *reinterpret_cast<uint4*>(hw);
    uint4 z = make_uint4(0,0,0,0);
    *reinterpret_cast<uint4*>(g_inhi + base + 104) = z;
    if (t == 0){
        const float* hp = h0 + (size_t)b*Fch*HW + p;
        for (int g = 0; g < 12; g++){
            #pragma unroll
            for (int q = 0; q < 4; q++)
                hw[q] = pack2(hp[(size_t)(g*8 + 2*q)*HW], hp[(size_t)(g*8 + 2*q+1)*HW]);
            *reinterpret_cast<uint4*>(g_inhi + base + 8 + g*8) = *reinterpret_cast<uint4*>(hw);
        }
    }
}

// ============================================================
// k_prepWall (once): conv-weight repacks (fp16)
// ============================================================
__global__ void k_prepWall(const float* __restrict__ w_i2f, const float* __restrict__ w_h2f,
                           const float* __restrict__ w_fl,  const float* __restrict__ w_i2h){
    int idx = blockIdx.x*blockDim.x + threadIdx.x;
    if (idx < 89600){
        int o = idx;
        int kc = o & 15, oc = (o >> 4) & 31, tap = (o >> 9) % 25, chunk = o / 12800;
        int ch = chunk*16 + kc;
        float v = 0.f;
        if (ch < 8)        v = w_i2f[(oc*8 + ch)*25 + tap];
        else if (ch < 104) v = w_h2f[((size_t)oc*Fch + (ch-8))*25 + tap];
        g_wfhi[o] = __float2half(v);
    } else if (idx < 89600 + 25600){
        int o = idx - 89600;
        int kc = o & 15, oc = (o >> 4) & 31, tap = (o >> 9) % 25, chunk = o / 12800;
        int ch = chunk*16 + kc;
        float v = (oc < 10) ? w_fl[((size_t)oc*32 + ch)*25 + tap] : 0.f;
        g_w2hi[o] = __float2half(v);
    } else if (idx < 89600 + 25600 + 20736){
        int o = idx - 89600 - 25600;
        int ch = o & 7, oc = (o >> 3) % 96, tap = (o/(96*8)) % 9, ocg = o/(9*96*8);
        float v = w_i2h[((size_t)(ocg*96 + oc)*CIN + ch)*9 + tap];
        g_w3hi[o] = __float2half(v);
    }
}

// ============================================================
// i2h implicit GEMM (m16n8k8, fp16 1-term), per-timestep chunks on s2.
// 2 IMAGES per CTA. grid (48, 2), 256 thr.
// ============================================================
__global__ void __launch_bounds__(256, 2) k_i2hT(int img0, const float* __restrict__ bias){
    __shared__ __half sInH[2][400*8];
    __shared__ __half sWH[9*96*8];
    uint32_t aIn0 = smem_u32(sInH[0]);
    uint32_t aWH  = smem_u32(sWH);

    int tid = threadIdx.x, lane = tid & 31, wid = tid >> 5;
    int wm = wid & 3, wn = wid >> 2;
    int y0 = blockIdx.x*2;
    int imgb = img0 + blockIdx.y*2;

    for (int e = tid; e < 800; e += 256){
        int im = e/400, ent = e%400;
        int row = ent/100, cc = ent%100;
        int y = y0 + row - 1, x = cc - 1;
        uint4 vh = make_uint4(0,0,0,0);
        if ((unsigned)y < 96u && (unsigned)x < 96u)
            vh = *reinterpret_cast<const uint4*>(g_inhi + ((size_t)(imgb+im)*HW + y*Ww + x)*CH);
        *reinterpret_cast<uint4*>(sInH[im] + ent*8) = vh;
    }

    #pragma unroll 1
    for (int ocg = 0; ocg < 3; ocg++){
        __syncthreads();
        for (int e = tid; e < 864; e += 256){
            reinterpret_cast<uint4*>(sWH)[e] = reinterpret_cast<const uint4*>(g_w3hi + (size_t)ocg*9*96*8)[e];
        }
        __syncthreads();

        #pragma unroll 1
        for (int im = 0; im < 2; im++){
            uint32_t aInH = aIn0 + (uint32_t)im*(400*8*2);
            float c[3][6][4];
            #pragma unroll
            for (int i = 0; i < 3; i++)
                #pragma unroll
                for (int j = 0; j < 6; j++)
                    #pragma unroll
                    for (int q = 0; q < 4; q++) c[i][j][q] = 0.f;

            #pragma unroll 1
            for (int tap = 0; tap < 9; tap++){
                int dy = tap/3, dx = tap%3;
                uint32_t bh[6];
                {
                    ldm_x4(bh, aWH + 2u*(uint32_t)((tap*96 + wn*48 + lane)*8));
                    uint32_t a2 = 2u*(uint32_t)((tap*96 + wn*48 + 32 + (lane & 15))*8);
                    ldm_x2(bh + 4, aWH + a2);
                }
                uint32_t ah[3][2];
                #pragma unroll
                for (int mi = 0; mi < 3; mi++){
                    int tmi = wm*3 + mi;
                    int r = tmi/6, xb = (tmi%6)*16;
                    uint32_t aoff = 2u*(uint32_t)(((r+dy)*100 + xb + (lane&15) + dx)*8);
                    ldm_x2(ah[mi], aInH + aoff);
                }
                #pragma unroll
                for (int mi = 0; mi < 3; mi++){
                    #pragma unroll
                    for (int j = 0; j < 6; j++){
                        MMA_F16_K8(c[mi][j], ah[mi], bh[j]);
                    }
                }
            }

            __half* Ob = g_i2h + (size_t)(imgb+im)*FH3*HW;
            #pragma unroll
            for (int mi = 0; mi < 3; mi++){
                int tmi = wm*3 + mi;
                int r = tmi/6, xb = (tmi%6)*16;
                int p = (y0 + r)*Ww + xb + (lane>>2);
                #pragma unroll
                for (int j = 0; j < 6; j++){
                    int oc = ocg*96 + wn*48 + j*8 + (lane&3)*2;
                    float bv0 = bias[oc], bv1 = bias[oc+1];
                    Ob[(size_t)oc*HW + p]         = __float2half(c[mi][j][0] + bv0);
                    Ob[(size_t)(oc+1)*HW + p]     = __float2half(c[mi][j][1] + bv1);
                    Ob[(size_t)oc*HW + p + 8]     = __float2half(c[mi][j][2] + bv0);
                    Ob[(size_t)(oc+1)*HW + p + 8] = __float2half(c[mi][j][3] + bv1);
                }
            }
        }
    }
}

// ============================================================
// fconv implicit GEMM — 1-term fp16. CTA = 2 rows x 96 px, N=32.
// ============================================================
#define FSM_BYTES ((14400 + 12800)*2)

__global__ void __launch_bounds__(256, 2) k_fconv(int t,
                                                  const float* __restrict__ b_i2f,
                                                  const float* __restrict__ b_h2f){
    extern __shared__ __half sm[];
    __half* sInH = sm;
    __half* sWH  = sm + 14400;
    uint32_t aInH = smem_u32(sInH), aWH = smem_u32(sWH);

    int tid = threadIdx.x, lane = tid & 31, wid = tid >> 5;
    int wm = wid & 3, wn = wid >> 2;
    int y0 = blockIdx.x*2, b = blockIdx.y;
    size_t slot = (size_t)(t*Bg + b)*HW;

    float c[3][2][4];
    #pragma unroll
    for (int i = 0; i < 3; i++)
        #pragma unroll
        for (int j = 0; j < 2; j++)
            #pragma unroll
            for (int q = 0; q < 4; q++) c[i][j][q] = 0.f;

    for (int chunk = 0; chunk < 7; chunk++){
        __syncthreads();
        for (int e = tid; e < 1200; e += 256){
            int ent = e >> 1, half_ = e & 1;
            int row = ent/100, cc = ent%100;
            int y = y0 + row - 2, x = cc - 2;
            uint4 vh = make_uint4(0,0,0,0);
            if ((unsigned)y < 96u && (unsigned)x < 96u){
                size_t off = (slot + y*Ww + x)*CH + chunk*16 + half_*8;
                vh = *reinterpret_cast<const uint4*>(g_inhi + off);
            }
            *reinterpret_cast<uint4*>(sInH + ent*24 + half_*8) = vh;
        }
        for (int e = tid; e < 1600; e += 256){
            reinterpret_cast<uint4*>(sWH)[e] = reinterpret_cast<const uint4*>(g_wfhi + chunk*12800)[e];
        }
        __syncthreads();

        #pragma unroll 1
        for (int tap = 0; tap < 25; tap++){
            int dy = tap/5, dx = tap%5;
            uint32_t bh[4];
            uint32_t boff = 2u*(uint32_t)((tap*32 + wn*16 + (lane&7) + ((lane>>4)&1)*8)*16
                                          + ((lane>>3)&1)*8);
            ldm_x4(bh, aWH + boff);
            uint32_t ah[3][4];
            #pragma unroll
            for (int mi = 0; mi < 3; mi++){
                int tmi = wm*3 + mi;
                int r = tmi/6, xb = (tmi%6)*16;
                uint32_t aoff = 2u*(uint32_t)(((r+dy)*100 + xb + (lane&15) + dx)*24
                                              + (lane>>4)*8);
                ldm_x4(ah[mi], aInH + aoff);
            }
            #pragma unroll
            for (int mi = 0; mi < 3; mi++){
                #pragma unroll
                for (int j = 0; j < 2; j++){
                    MMA_F16(c[mi][j], ah[mi], &bh[j*2]);
                }
            }
        }
    }

    #pragma unroll
    for (int mi = 0; mi < 3; mi++){
        int tmi = wm*3 + mi;
        int r = tmi/6, xb = (tmi%6)*16;
        int gp = (y0 + r)*Ww + xb + (lane>>2);
        #pragma unroll
        for (int j = 0; j < 2; j++){
            int oc = wn*16 + j*8 + (lane&3)*2;
            float bb0 = b_i2f[oc]   + b_h2f[oc];
            float bb1 = b_i2f[oc+1] + b_h2f[oc+1];
            *reinterpret_cast<uint32_t*>(g_fhi + ((size_t)b*HW + gp)*32 + oc)
                = pack2(leaky(c[mi][j][0] + bb0), leaky(c[mi][j][1] + bb1));
            *reinterpret_cast<uint32_t*>(g_fhi + ((size_t)b*HW + gp + 8)*32 + oc)
                = pack2(leaky(c[mi][j][2] + bb0), leaky(c[mi][j][3] + bb1));
        }
    }
}

// ============================================================
// flowsT + FUSED warp. grid (48, B), 256 thr
// ============================================================
__global__ void __launch_bounds__(256, 2) k_flowsW(int t, const float* __restrict__ b_fl){
    extern __shared__ __half sm[];
    __half* sInH = sm;
    __half* sWH  = sm + 14400;
    uint32_t aInH = smem_u32(sInH), aWH = smem_u32(sWH);

    int tid = threadIdx.x, lane = tid & 31, wid = tid >> 5;
    int wm = wid & 3, wn = wid >> 2;
    int y0 = blockIdx.x*2, b = blockIdx.y;

    float c[3][2][4];
    #pragma unroll
    for (int i = 0; i < 3; i++)
        #pragma unroll
        for (int j = 0; j < 2; j++)
            #pragma unroll
            for (int q = 0; q < 4; q++) c[i][j][q] = 0.f;

    for (int chunk = 0; chunk < 2; chunk++){
        __syncthreads();
        for (int e = tid; e < 1200; e += 256){
            int ent = e >> 1, half_ = e & 1;
            int row = ent/100, cc = ent%100;
            int y = y0 + row - 2, x = cc - 2;
            uint4 vh = make_uint4(0,0,0,0);
            if ((unsigned)y < 96u && (unsigned)x < 96u){
                size_t off = ((size_t)b*HW + y*Ww + x)*32 + chunk*16 + half_*8;
                vh = *reinterpret_cast<const uint4*>(g_fhi + off);
            }
            *reinterpret_cast<uint4*>(sInH + ent*24 + half_*8) = vh;
        }
        for (int e = tid; e < 1600; e += 256){
            reinterpret_cast<uint4*>(sWH)[e] = reinterpret_cast<const uint4*>(g_w2hi + chunk*12800)[e];
        }
        __syncthreads();

        #pragma unroll 1
        for (int tap = 0; tap < 25; tap++){
            int dy = tap/5, dx = tap%5;
            uint32_t bh[4];
            uint32_t boff = 2u*(uint32_t)((tap*32 + wn*16 + (lane&7) + ((lane>>4)&1)*8)*16
                                          + ((lane>>3)&1)*8);
            ldm_x4(bh, aWH + boff);
            uint32_t ah[3][4];
            #pragma unroll
            for (int mi = 0; mi < 3; mi++){
                int tmi = wm*3 + mi;
                int r = tmi/6, xb = (tmi%6)*16;
                uint32_t aoff = 2u*(uint32_t)(((r+dy)*100 + xb + (lane&15) + dx)*24
                                              + (lane>>4)*8);
                ldm_x4(ah[mi], aInH + aoff);
            }
            #pragma unroll
            for (int mi = 0; mi < 3; mi++){
                #pragma unroll
                for (int j = 0; j < 2; j++){
                    MMA_F16(c[mi][j], ah[mi], &bh[j*2]);
                }
            }
        }
    }

    // ---- stage flows into smem [192 px][10] (aliases sInH) ----
    __syncthreads();
    float* sFl = reinterpret_cast<float*>(sm);
    #pragma unroll
    for (int mi = 0; mi < 3; mi++){
        int tmi = wm*3 + mi;
        int r = tmi/6, xb = (tmi%6)*16;
        int pl = r*96 + xb + (lane>>2);
        #pragma unroll
        for (int j = 0; j < 2; j++){
            int oc = wn*16 + j*8 + (lane&3)*2;
            if (oc < 10){
                float bv0 = b_fl[oc], bv1 = b_fl[oc+1];
                sFl[pl*10 + oc]         = c[mi][j][0] + bv0;
                sFl[pl*10 + oc + 1]     = c[mi][j][1] + bv1;
                sFl[(pl+8)*10 + oc]     = c[mi][j][2] + bv0;
                sFl[(pl+8)*10 + oc + 1] = c[mi][j][3] + bv1;
            }
        }
    }
    __syncthreads();

    // ---- fused warp: tasks ordered link-major for gather locality ----
    const __half* hb = g_inhi + (size_t)(t*Bg + b)*HW*CH + 8;
    const float scg = 96.0f/95.0f;
    for (int task = tid; task < 960; task += 256){
        int l = task/192, px = task%192;
        int y = y0 + px/96, x = px%96;
        float fx = sFl[px*10 + 2*l];
        float fy = sFl[px*10 + 2*l + 1];
        float ix = ((float)x - fx)*scg - 0.5f;
        float iy = ((float)y - fy)*scg - 0.5f;
        float fx0 = floorf(ix), fy0 = floorf(iy);
        int ix0 = (int)fx0, iy0 = (int)fy0;
        int ix1 = ix0 + 1, iy1 = iy0 + 1;
        float wx1 = ix - fx0, wy1 = iy - fy0;
        float wx0 = 1.f - wx1, wy0 = 1.f - wy1;
        float mx0 = (ix0 >= 0 && ix0 < Ww) ? 1.f : 0.f;
        float mx1 = (ix1 >= 0 && ix1 < Ww) ? 1.f : 0.f;
        float my0 = (iy0 >= 0 && iy0 < Hh) ? 1.f : 0.f;
        float my1 = (iy1 >= 0 && iy1 < Hh) ? 1.f : 0.f;
        int cx0 = min(max(ix0, 0), Ww-1), cx1 = min(max(ix1, 0), Ww-1);
        int cy0 = min(max(iy0, 0), Hh-1), cy1 = min(max(iy1, 0), Hh-1);
        float w00 = wy0*wx0*my0*mx0, w01 = wy0*wx1*my0*mx1;
        float w10 = wy1*wx0*my1*mx0, w11 = wy1*wx1*my1*mx1;
        const __half* p00 = hb + (size_t)(cy0*Ww + cx0)*CH;
        const __half* p01 = hb + (size_t)(cy0*Ww + cx1)*CH;
        const __half* p10 = hb + (size_t)(cy1*Ww + cx0)*CH;
        const __half* p11 = hb + (size_t)(cy1*Ww + cx1)*CH;
        __half* op = g_whi + ((size_t)b*HW + y*Ww + x)*KPAD + (size_t)l*Fch;
        #pragma unroll 1
        for (int cg = 0; cg < 12; cg++){
            uint4 v00 = *reinterpret_cast<const uint4*>(p00 + cg*8);
            uint4 v01 = *reinterpret_cast<const uint4*>(p01 + cg*8);
            uint4 v10 = *reinterpret_cast<const uint4*>(p10 + cg*8);
            uint4 v11 = *reinterpret_cast<const uint4*>(p11 + cg*8);
            const uint32_t* a00 = reinterpret_cast<const uint32_t*>(&v00);
            const uint32_t* a01 = reinterpret_cast<const uint32_t*>(&v01);
            const uint32_t* a10 = reinterpret_cast<const uint32_t*>(&v10);
            const uint32_t* a11 = reinterpret_cast<const uint32_t*>(&v11);
            uint32_t outw[4];
            #pragma unroll
            for (int q = 0; q < 4; q++){
                float2 f00 = __half22float2(*reinterpret_cast<const __half2*>(&a00[q]));
                float2 f01 = __half22float2(*reinterpret_cast<const __half2*>(&a01[q]));
                float2 f10 = __half22float2(*reinterpret_cast<const __half2*>(&a10[q]));
                float2 f11 = __half22float2(*reinterpret_cast<const __half2*>(&a11[q]));
                float r0 = w00*f00.x + w01*f01.x + w10*f10.x + w11*f11.x;
                float r1 = w00*f00.y + w01*f01.y + w10*f10.y + w11*f11.y;
                outw[q] = pack2(r0, r1);
            }
            *reinterpret_cast<uint4*>(op + cg*8) = *reinterpret_cast<uint4*>(outw);
        }
    }
}

// ============================================================
// prep: w_ret hi (288 x 480, stride KPAD) fp16
// ============================================================
__global__ void k_prepA(const float* __restrict__ w_ret){
    int idx = blockIdx.x*blockDim.x + threadIdx.x;
    if (idx >= FH3*KPAD) return;
    int m = idx / KPAD, k = idx % KPAD;
    float v = (k < K1) ? w_ret[m*K1 + k] : 0.f;
    g_Ahi[idx] = __float2half(v);
}

// ============================================================
// FUSED h2h GEMM (1-term fp16) + GRU gates.
// grid (72, B), 256 thr, dyn smem 66.6 KB
// ============================================================
#define TS 40
#define H2_ABUF (288*TS)
#define H2_BBUF (128*TS)
#define H2_SMEM ((2*H2_ABUF + 2*H2_BBUF)*2)   // 66560 B

__global__ void __launch_bounds__(256, 1) k_h2hg(int t,
                                                 const float* __restrict__ bias,
                                                 const float* __restrict__ hprev,
                                                 float* __restrict__ hnext,
                                                 int pack){
    extern __shared__ __half sm[];
    __half* sAh = sm;
    __half* sBh = sm + 2*H2_ABUF;
    uint32_t aSh = smem_u32(sAh), aBh = smem_u32(sBh);

    int tid = threadIdx.x, lane = tid & 31, wid = tid >> 5;
    int wm = wid & 1, wn = wid >> 1;
    int n0 = blockIdx.x*128, b = blockIdx.y;

    const __half* Bh = g_whi + ((size_t)b*HW + n0)*KPAD;

    int arow = wm*48 + (lane & 15);
    int acol = (lane >> 4) * 8;
    int brow = wn*32 + (lane & 7) + ((lane >> 4) & 1)*8;
    int bcol = ((lane >> 3) & 1) * 8;

    float c[3][3][4][4];
    #pragma unroll
    for (int mt = 0; mt < 3; mt++)
        #pragma unroll
        for (int i = 0; i < 3; i++)
            #pragma unroll
            for (int j = 0; j < 4; j++)
                #pragma unroll
                for (int q = 0; q < 4; q++) c[mt][i][j][q] = 0.f;

    #define H2G_STAGE(chunk, buf) do { \
        uint32_t sbA = (uint32_t)(buf)*(H2_ABUF*2); \
        uint32_t sbB = (uint32_t)(buf)*(H2_BBUF*2); \
        for (int e = tid; e < 1152; e += 256){ \
            int r = e >> 2, u = e & 3; \
            size_t goff = (size_t)r*KPAD + (chunk)*32 + u*8; \
            uint32_t soff = sbA + (uint32_t)(r*TS + u*8)*2u; \
            CPA16(aSh + soff, g_Ahi + goff); \
        } \
        for (int e = tid; e < 512; e += 256){ \
            int r = e >> 2, u = e & 3; \
            size_t goff = (size_t)r*KPAD + (chunk)*32 + u*8; \
            uint32_t soff = sbB + (uint32_t)(r*TS + u*8)*2u; \
            CPA16(aBh + soff, Bh + goff); \
        } \
        CPA_COMMIT(); \
    } while(0)

    H2G_STAGE(0, 0);
    for (int chunk = 0; chunk < 15; chunk++){
        if (chunk + 1 < 15){
            H2G_STAGE(chunk + 1, (chunk + 1) & 1);
            asm volatile("cp.async.wait_group 1;" ::: "memory");
        } else {
            asm volatile("cp.async.wait_group 0;" ::: "memory");
        }
        __syncthreads();

        uint32_t sbA = (uint32_t)(chunk & 1)*(H2_ABUF*2);
        uint32_t sbB = (uint32_t)(chunk & 1)*(H2_BBUF*2);
        #pragma unroll
        for (int ks = 0; ks < 2; ks++){
            int kc = ks*16;
            uint32_t bh[2][4];
            #pragma unroll
            for (int jp = 0; jp < 2; jp++){
                uint32_t off = sbB + 2u*((brow + jp*16)*TS + kc + bcol);
                ldm_x4(bh[jp], aBh + off);
            }
            #pragma unroll
            for (int mt = 0; mt < 3; mt++){
                uint32_t ah[3][4];
                #pragma unroll
                for (int mi = 0; mi < 3; mi++){
                    uint32_t off = sbA + 2u*((mt*96 + arow + mi*16)*TS + kc + acol);
                    ldm_x4(ah[mi], aSh + off);
                }
                #pragma unroll
                for (int mi = 0; mi < 3; mi++){
                    #pragma unroll
                    for (int j = 0; j < 4; j++){
                        uint32_t* fh = &bh[j >> 1][(j & 1)*2];
                        MMA_F16(c[mt][mi][j], ah[mi], fh);
                    }
                }
            }
        }
        __syncthreads();
    }

    // ---- fused GRU gate epilogue ----
    __syncthreads();
    float* sF = reinterpret_cast<float*>(sm);   // [128 px][stride 100]

    const __half* i2hb = g_i2h + (size_t)(t*Bg + b)*FH3*HW;
    const float* hpb  = hprev + (size_t)b*Fch*HW;
    float* hnb        = hnext + (size_t)b*Fch*HW;

    #pragma unroll
    for (int mi = 0; mi < 3; mi++){
        int fc0 = wm*48 + mi*16 + (lane >> 2);
        #pragma unroll
        for (int j = 0; j < 4; j++){
            int pl = wn*32 + (lane & 3)*2 + j*8;
            int p = n0 + pl;
            #pragma unroll
            for (int half_ = 0; half_ < 2; half_++){
                int fc = fc0 + half_*8;
                int q0 = half_*2;
                float rb = bias[fc], ub = bias[96 + fc], mb = bias[192 + fc];
                float2 i2r = __half22float2(*reinterpret_cast<const __half2*>(i2hb + (size_t)fc*HW + p));
                float2 i2u = __half22float2(*reinterpret_cast<const __half2*>(i2hb + (size_t)(96+fc)*HW + p));
                float2 i2m = __half22float2(*reinterpret_cast<const __half2*>(i2hb + (size_t)(192+fc)*HW + p));
                float2 hpv = *reinterpret_cast<const float2*>(hpb + (size_t)fc*HW + p);
                float nh[2];
                #pragma unroll
                for (int s = 0; s < 2; s++){
                    float hr = c[0][mi][j][q0+s] + rb;
                    float hu = c[1][mi][j][q0+s] + ub;
                    float hm = c[2][mi][j][q0+s] + mb;
                    float ir = s ? i2r.y : i2r.x;
                    float iu = s ? i2u.y : i2u.x;
                    float im = s ? i2m.y : i2m.x;
                    float hp = s ? hpv.y : hpv.x;
                    float reset  = sigm(ir + hr);
                    float update = sigm(iu + hu);
                    float newmem = leaky(im + reset*hm);
                    nh[s] = update*hp + (1.f - update)*newmem;
                }
                float2 wv; wv.x = nh[0]; wv.y = nh[1];
                *reinterpret_cast<float2*>(hnb + (size_t)fc*HW + p) = wv;
                sF[pl*100 + fc]     = nh[0];
                sF[(pl+1)*100 + fc] = nh[1];
            }
        }
    }
    __syncthreads();
    if (pack){
        size_t slotn = (size_t)((t+1)*Bg + b)*HW;
        for (int e = tid; e < 128*12; e += 256){
            int pl = e/12, u = e%12;
            const float* src = sF + pl*100 + u*8;
            uint32_t hw[4];
            #pragma unroll
            for (int q = 0; q < 4; q++)
                hw[q] = pack2(src[2*q], src[2*q+1]);
            size_t off = (slotn + n0 + pl)*CH + 8 + u*8;
            *reinterpret_cast<uint4*>(g_inhi + off) = *reinterpret_cast<uint4*>(hw);
        }
    }
}

// ============================================================
extern "C" void kernel_launch(void* const* d_in, const int* in_sizes, int n_in,
                              void* d_out, int out_size){
    const float* inputs = (const float*)d_in[0];
    const float* h0     = (const float*)d_in[1];
    const float* w_i2h  = (const float*)d_in[2];
    const float* b_i2h  = (const float*)d_in[3];
    const float* w_i2f  = (const float*)d_in[4];
    const float* b_i2f  = (const float*)d_in[5];
    const float* w_h2f  = (const float*)d_in[6];
    const float* b_h2f  = (const float*)d_in[7];
    const float* w_fl   = (const float*)d_in[8];
    const float* b_fl   = (const float*)d_in[9];
    const float* w_ret  = (const float*)d_in[10];
    const float* b_ret  = (const float*)d_in[11];
    float* out = (float*)d_out;

    static cudaStream_t s2 = nullptr;
    static cudaEvent_t evRoot = nullptr;
    static cudaEvent_t evI[Sg];
    if (!s2){
        cudaStreamCreateWithFlags(&s2, cudaStreamNonBlocking);
        cudaEventCreateWithFlags(&evRoot, cudaEventDisableTiming);
        for (int t = 0; t < Sg; t++)
            cudaEventCreateWithFlags(&evI[t], cudaEventDisableTiming);
        cudaFuncSetAttribute(k_fconv,  cudaFuncAttributeMaxDynamicSharedMemorySize, FSM_BYTES);
        cudaFuncSetAttribute(k_flowsW, cudaFuncAttributeMaxDynamicSharedMemorySize, FSM_BYTES);
        cudaFuncSetAttribute(k_h2hg,   cudaFuncAttributeMaxDynamicSharedMemorySize, H2_SMEM);
    }

    k_prepX   <<<(Sg*Bg*HW + 255)/256, 256>>>(inputs, h0);
    k_prepWall<<<(89600 + 25600 + 20736 + 255)/256, 256>>>(w_i2f, w_h2f, w_fl, w_i2h);
    k_prepA   <<<(FH3*KPAD + 255)/256, 256>>>(w_ret);

    cudaEventRecord(evRoot, 0);
    cudaStreamWaitEvent(s2, evRoot, 0);
    for (int t = 0; t < Sg; t++){
        k_i2hT<<<dim3(48, 2), 256, 0, s2>>>(t*Bg, b_i2h);
        cudaEventRecord(evI[t], s2);
    }

    for (int t = 0; t < Sg; t++){
        const float* h = (t == 0) ? h0 : out + (size_t)(t-1)*STEP_ELEMS;
        float* hn = out + (size_t)t*STEP_ELEMS;

        k_fconv <<<dim3(48, Bg), 256, FSM_BYTES>>>(t, b_i2f, b_h2f);
        k_flowsW<<<dim3(48, Bg), 256, FSM_BYTES>>>(t, b_fl);
        cudaStreamWaitEvent(0, evI[t], 0);
        k_h2hg  <<<dim3(HW/128, Bg), 256, H2_SMEM>>>(t, b_ret, h, hn, (t < Sg-1) ? 1 : 0);
    }

    const size_t OUT_SEQ = (size_t)Sg*STEP_ELEMS;
    if ((size_t)out_size >= OUT_SEQ + STEP_ELEMS){
        cudaMemcpyAsync(out + OUT_SEQ, out + (size_t)(Sg-1)*STEP_ELEMS,
                        (size_t)STEP_ELEMS*sizeof(float),
                        cudaMemcpyDeviceToDevice);
    }
}

// round 16
// speedup vs baseline: 1.0843x; 1.0843x over previous
#include <cuda_runtime.h>
#include <cuda_fp16.h>
#include <cstdint>
#include <math.h>

#define Hh 96
#define Ww 96
#define HW 9216
#define Fch 96
#define CIN 8
#define Lk 5
#define Sg 10
#define Bg 4
#define FH3 288          // 3*F
#define K1 480           // L*F
#define KPAD 512         // row STRIDE of k-major operands (pad cols never read)
#define CH 112           // packed input channels: 8 x | 96 h | 8 zero
#define STEP_ELEMS (Bg*Fch*HW)   // 3,538,944

// ---- scratch (device globals) ----
__device__ __align__(16) __half g_i2h[(size_t)Sg*Bg*FH3*HW];  // 212 MB (once), fp16
__device__ __align__(16) __half g_whi[(size_t)Bg*HW*KPAD];    // warped^T hi [b][p][k]
__device__ __align__(16) __half g_Ahi[(size_t)FH3*KPAD];      // w_ret hi [m][k]
// fconv inputs: per-step slots [Sg][Bg][p][112] (hi only)
__device__ __align__(16) __half g_inhi[(size_t)Sg*Bg*HW*CH];
__device__ __align__(16) __half g_wfhi[7*25*32*16];           // [chunk][tap][oc][16]
// f (1-term) [b][p][32]
__device__ __align__(16) __half g_fhi[(size_t)Bg*HW*32];
// flows weights [chunk2][tap25][oc32][16] (oc>=10 zero)
__device__ __align__(16) __half g_w2hi[2*25*32*16];
// i2h weights [ocg3][tap9][oc96][8] (1-term)
__device__ __align__(16) __half g_w3hi[3*9*96*8];

__device__ __forceinline__ float leaky(float v){ return v > 0.f ? v : 0.2f*v; }
__device__ __forceinline__ float sigm(float v){ return 1.f/(1.f + expf(-v)); }

__device__ __forceinline__ uint32_t smem_u32(const void* p){
    uint32_t a;
    asm("{ .reg .u64 t; cvta.to.shared.u64 t, %1; cvt.u32.u64 %0, t; }" : "=r"(a) : "l"(p));
    return a;
}
__device__ __forceinline__ void ldm_x4(uint32_t* r, uint32_t addr){
    asm volatile("ldmatrix.sync.aligned.m8n8.x4.shared.b16 {%0,%1,%2,%3}, [%4];"
        : "=r"(r[0]), "=r"(r[1]), "=r"(r[2]), "=r"(r[3]) : "r"(addr));
}
__device__ __forceinline__ void ldm_x2(uint32_t* r, uint32_t addr){
    asm volatile("ldmatrix.sync.aligned.m8n8.x2.shared.b16 {%0,%1}, [%2];"
        : "=r"(r[0]), "=r"(r[1]) : "r"(addr));
}
#define MMA_F16(c, a, b) \
    asm volatile("mma.sync.aligned.m16n8k16.row.col.f32.f16.f16.f32 " \
        "{%0,%1,%2,%3}, {%4,%5,%6,%7}, {%8,%9}, {%0,%1,%2,%3};" \
        : "+f"((c)[0]), "+f"((c)[1]), "+f"((c)[2]), "+f"((c)[3]) \
        : "r"((a)[0]), "r"((a)[1]), "r"((a)[2]), "r"((a)[3]), \
          "r"((b)[0]), "r"((b)[1]))
#define MMA_F16_K8(c, a, b) \
    asm volatile("mma.sync.aligned.m16n8k8.row.col.f32.f16.f16.f32 " \
        "{%0,%1,%2,%3}, {%4,%5}, {%6}, {%0,%1,%2,%3};" \
        : "+f"((c)[0]), "+f"((c)[1]), "+f"((c)[2]), "+f"((c)[3]) \
        : "r"((a)[0]), "r"((a)[1]), "r"(b))
#define CPA16(sm, gp) asm volatile("cp.async.ca.shared.global [%0], [%1], 16;" :: "r"(sm), "l"(gp))
#define CPA_COMMIT()  asm volatile("cp.async.commit_group;" ::: "memory")

__device__ __forceinline__ uint32_t pack2(float v0, float v1){
    __half2 hp = __halves2half2(__float2half(v0), __float2half(v1));
    return *reinterpret_cast<uint32_t*>(&hp);
}

// ============================================================
// k_prepX (once): pack x channels (hi) for ALL step slots, zero pad,
// slot-0 h channels from h0.
// ============================================================
__global__ void k_prepX(const float* __restrict__ inputs, const float* __restrict__ h0){
    int idx = blockIdx.x*blockDim.x + threadIdx.x;
    if (idx >= Sg*Bg*HW) return;
    int p = idx % HW, b = (idx/HW) % Bg, t = idx/(HW*Bg);
    size_t base = ((size_t)(t*Bg + b)*HW + p)*CH;
    const float* xp = inputs + ((size_t)(t*Bg + b)*CIN)*HW + p;
    uint32_t hw[4];
    #pragma unroll
    for (int q = 0; q < 4; q++)
        hw[q] = pack2(xp[(size_t)(2*q)*HW], xp[(size_t)(2*q+1)*HW]);
    *reinterpret_cast<uint4*>(g_inhi + base) = *reinterpret_cast<uint4*>(hw);
    uint4 z = make_uint4(0,0,0,0);
    *reinterpret_cast<uint4*>(g_inhi + base + 104) = z;
    if (t == 0){
        const float* hp = h0 + (size_t)b*Fch*HW + p;
        for (int g = 0; g < 12; g++){
            #pragma unroll
            for (int q = 0; q < 4; q++)
                hw[q] = pack2(hp[(size_t)(g*8 + 2*q)*HW], hp[(size_t)(g*8 + 2*q+1)*HW]);
            *reinterpret_cast<uint4*>(g_inhi + base + 8 + g*8) = *reinterpret_cast<uint4*>(hw);
        }
    }
}

// ============================================================
// k_prepWall (once): conv-weight repacks (fp16)
// ============================================================
__global__ void k_prepWall(const float* __restrict__ w_i2f, const float* __restrict__ w_h2f,
                           const float* __restrict__ w_fl,  const float* __restrict__ w_i2h){
    int idx = blockIdx.x*blockDim.x + threadIdx.x;
    if (idx < 89600){
        int o = idx;
        int kc = o & 15, oc = (o >> 4) & 31, tap = (o >> 9) % 25, chunk = o / 12800;
        int ch = chunk*16 + kc;
        float v = 0.f;
        if (ch < 8)        v = w_i2f[(oc*8 + ch)*25 + tap];
        else if (ch < 104) v = w_h2f[((size_t)oc*Fch + (ch-8))*25 + tap];
        g_wfhi[o] = __float2half(v);
    } else if (idx < 89600 + 25600){
        int o = idx - 89600;
        int kc = o & 15, oc = (o >> 4) & 31, tap = (o >> 9) % 25, chunk = o / 12800;
        int ch = chunk*16 + kc;
        float v = (oc < 10) ? w_fl[((size_t)oc*32 + ch)*25 + tap] : 0.f;
        g_w2hi[o] = __float2half(v);
    } else if (idx < 89600 + 25600 + 20736){
        int o = idx - 89600 - 25600;
        int ch = o & 7, oc = (o >> 3) % 96, tap = (o/(96*8)) % 9, ocg = o/(9*96*8);
        float v = w_i2h[((size_t)(ocg*96 + oc)*CIN + ch)*9 + tap];
        g_w3hi[o] = __float2half(v);
    }
}

// ============================================================
// i2h implicit GEMM (m16n8k8, fp16 1-term), per-timestep chunks on s2.
// 2 IMAGES per CTA. grid (48, 2), 256 thr.
// ============================================================
__global__ void __launch_bounds__(256, 2) k_i2hT(int img0, const float* __restrict__ bias){
    __shared__ __half sInH[2][400*8];
    __shared__ __half sWH[9*96*8];
    uint32_t aIn0 = smem_u32(sInH[0]);
    uint32_t aWH  = smem_u32(sWH);

    int tid = threadIdx.x, lane = tid & 31, wid = tid >> 5;
    int wm = wid & 3, wn = wid >> 2;
    int y0 = blockIdx.x*2;
    int imgb = img0 + blockIdx.y*2;

    for (int e = tid; e < 800; e += 256){
        int im = e/400, ent = e%400;
        int row = ent/100, cc = ent%100;
        int y = y0 + row - 1, x = cc - 1;
        uint4 vh = make_uint4(0,0,0,0);
        if ((unsigned)y < 96u && (unsigned)x < 96u)
            vh = *reinterpret_cast<const uint4*>(g_inhi + ((size_t)(imgb+im)*HW + y*Ww + x)*CH);
        *reinterpret_cast<uint4*>(sInH[im] + ent*8) = vh;
    }

    #pragma unroll 1
    for (int ocg = 0; ocg < 3; ocg++){
        __syncthreads();
        for (int e = tid; e < 864; e += 256){
            reinterpret_cast<uint4*>(sWH)[e] = reinterpret_cast<const uint4*>(g_w3hi + (size_t)ocg*9*96*8)[e];
        }
        __syncthreads();

        #pragma unroll 1
        for (int im = 0; im < 2; im++){
            uint32_t aInH = aIn0 + (uint32_t)im*(400*8*2);
            float c[3][6][4];
            #pragma unroll
            for (int i = 0; i < 3; i++)
                #pragma unroll
                for (int j = 0; j < 6; j++)
                    #pragma unroll
                    for (int q = 0; q < 4; q++) c[i][j][q] = 0.f;

            #pragma unroll 1
            for (int tap = 0; tap < 9; tap++){
                int dy = tap/3, dx = tap%3;
                uint32_t bh[6];
                {
                    ldm_x4(bh, aWH + 2u*(uint32_t)((tap*96 + wn*48 + lane)*8));
                    uint32_t a2 = 2u*(uint32_t)((tap*96 + wn*48 + 32 + (lane & 15))*8);
                    ldm_x2(bh + 4, aWH + a2);
                }
                uint32_t ah[3][2];
                #pragma unroll
                for (int mi = 0; mi < 3; mi++){
                    int tmi = wm*3 + mi;
                    int r = tmi/6, xb = (tmi%6)*16;
                    uint32_t aoff = 2u*(uint32_t)(((r+dy)*100 + xb + (lane&15) + dx)*8);
                    ldm_x2(ah[mi], aInH + aoff);
                }
                #pragma unroll
                for (int mi = 0; mi < 3; mi++){
                    #pragma unroll
                    for (int j = 0; j < 6; j++){
                        MMA_F16_K8(c[mi][j], ah[mi], bh[j]);
                    }
                }
            }

            __half* Ob = g_i2h + (size_t)(imgb+im)*FH3*HW;
            #pragma unroll
            for (int mi = 0; mi < 3; mi++){
                int tmi = wm*3 + mi;
                int r = tmi/6, xb = (tmi%6)*16;
                int p = (y0 + r)*Ww + xb + (lane>>2);
                #pragma unroll
                for (int j = 0; j < 6; j++){
                    int oc = ocg*96 + wn*48 + j*8 + (lane&3)*2;
                    float bv0 = bias[oc], bv1 = bias[oc+1];
                    Ob[(size_t)oc*HW + p]         = __float2half(c[mi][j][0] + bv0);
                    Ob[(size_t)(oc+1)*HW + p]     = __float2half(c[mi][j][1] + bv1);
                    Ob[(size_t)oc*HW + p + 8]     = __float2half(c[mi][j][2] + bv0);
                    Ob[(size_t)(oc+1)*HW + p + 8] = __float2half(c[mi][j][3] + bv1);
                }
            }
        }
    }
}

// ============================================================
// fconv implicit GEMM — 1-term fp16. CTA = 2 rows x 96 px, N=32.
// ============================================================
#define FSM_BYTES ((14400 + 12800)*2)

__global__ void __launch_bounds__(256, 2) k_fconv(int t,
                                                  const float* __restrict__ b_i2f,
                                                  const float* __restrict__ b_h2f){
    extern __shared__ __half sm[];
    __half* sInH = sm;
    __half* sWH  = sm + 14400;
    uint32_t aInH = smem_u32(sInH), aWH = smem_u32(sWH);

    int tid = threadIdx.x, lane = tid & 31, wid = tid >> 5;
    int wm = wid & 3, wn = wid >> 2;
    int y0 = blockIdx.x*2, b = blockIdx.y;
    size_t slot = (size_t)(t*Bg + b)*HW;

    float c[3][2][4];
    #pragma unroll
    for (int i = 0; i < 3; i++)
        #pragma unroll
        for (int j = 0; j < 2; j++)
            #pragma unroll
            for (int q = 0; q < 4; q++) c[i][j][q] = 0.f;

    for (int chunk = 0; chunk < 7; chunk++){
        __syncthreads();
        for (int e = tid; e < 1200; e += 256){
            int ent = e >> 1, half_ = e & 1;
            int row = ent/100, cc = ent%100;
            int y = y0 + row - 2, x = cc - 2;
            uint4 vh = make_uint4(0,0,0,0);
            if ((unsigned)y < 96u && (unsigned)x < 96u){
                size_t off = (slot + y*Ww + x)*CH + chunk*16 + half_*8;
                vh = *reinterpret_cast<const uint4*>(g_inhi + off);
            }
            *reinterpret_cast<uint4*>(sInH + ent*24 + half_*8) = vh;
        }
        for (int e = tid; e < 1600; e += 256){
            reinterpret_cast<uint4*>(sWH)[e] = reinterpret_cast<const uint4*>(g_wfhi + chunk*12800)[e];
        }
        __syncthreads();

        #pragma unroll 1
        for (int tap = 0; tap < 25; tap++){
            int dy = tap/5, dx = tap%5;
            uint32_t bh[4];
            uint32_t boff = 2u*(uint32_t)((tap*32 + wn*16 + (lane&7) + ((lane>>4)&1)*8)*16
                                          + ((lane>>3)&1)*8);
            ldm_x4(bh, aWH + boff);
            uint32_t ah[3][4];
            #pragma unroll
            for (int mi = 0; mi < 3; mi++){
                int tmi = wm*3 + mi;
                int r = tmi/6, xb = (tmi%6)*16;
                uint32_t aoff = 2u*(uint32_t)(((r+dy)*100 + xb + (lane&15) + dx)*24
                                              + (lane>>4)*8);
                ldm_x4(ah[mi], aInH + aoff);
            }
            #pragma unroll
            for (int mi = 0; mi < 3; mi++){
                #pragma unroll
                for (int j = 0; j < 2; j++){
                    MMA_F16(c[mi][j], ah[mi], &bh[j*2]);
                }
            }
        }
    }

    #pragma unroll
    for (int mi = 0; mi < 3; mi++){
        int tmi = wm*3 + mi;
        int r = tmi/6, xb = (tmi%6)*16;
        int gp = (y0 + r)*Ww + xb + (lane>>2);
        #pragma unroll
        for (int j = 0; j < 2; j++){
            int oc = wn*16 + j*8 + (lane&3)*2;
            float bb0 = b_i2f[oc]   + b_h2f[oc];
            float bb1 = b_i2f[oc+1] + b_h2f[oc+1];
            *reinterpret_cast<uint32_t*>(g_fhi + ((size_t)b*HW + gp)*32 + oc)
                = pack2(leaky(c[mi][j][0] + bb0), leaky(c[mi][j][1] + bb1));
            *reinterpret_cast<uint32_t*>(g_fhi + ((size_t)b*HW + gp + 8)*32 + oc)
                = pack2(leaky(c[mi][j][2] + bb0), leaky(c[mi][j][3] + bb1));
        }
    }
}

// ============================================================
// flowsT + FUSED warp. grid (48, B), 256 thr
// ============================================================
__global__ void __launch_bounds__(256, 2) k_flowsW(int t, const float* __restrict__ b_fl){
    extern __shared__ __half sm[];
    __half* sInH = sm;
    __half* sWH  = sm + 14400;
    uint32_t aInH = smem_u32(sInH), aWH = smem_u32(sWH);

    int tid = threadIdx.x, lane = tid & 31, wid = tid >> 5;
    int wm = wid & 3, wn = wid >> 2;
    int y0 = blockIdx.x*2, b = blockIdx.y;

    float c[3][2][4];
    #pragma unroll
    for (int i = 0; i < 3; i++)
        #pragma unroll
        for (int j = 0; j < 2; j++)
            #pragma unroll
            for (int q = 0; q < 4; q++) c[i][j][q] = 0.f;

    for (int chunk = 0; chunk < 2; chunk++){
        __syncthreads();
        for (int e = tid; e < 1200; e += 256){
            int ent = e >> 1, half_ = e & 1;
            int row = ent/100, cc = ent%100;
            int y = y0 + row - 2, x = cc - 2;
            uint4 vh = make_uint4(0,0,0,0);
            if ((unsigned)y < 96u && (unsigned)x < 96u){
                size_t off = ((size_t)b*HW + y*Ww + x)*32 + chunk*16 + half_*8;
                vh = *reinterpret_cast<const uint4*>(g_fhi + off);
            }
            *reinterpret_cast<uint4*>(sInH + ent*24 + half_*8) = vh;
        }
        for (int e = tid; e < 1600; e += 256){
            reinterpret_cast<uint4*>(sWH)[e] = reinterpret_cast<const uint4*>(g_w2hi + chunk*12800)[e];
        }
        __syncthreads();

        #pragma unroll 1
        for (int tap = 0; tap < 25; tap++){
            int dy = tap/5, dx = tap%5;
            uint32_t bh[4];
            uint32_t boff = 2u*(uint32_t)((tap*32 + wn*16 + (lane&7) + ((lane>>4)&1)*8)*16
                                          + ((lane>>3)&1)*8);
            ldm_x4(bh, aWH + boff);
            uint32_t ah[3][4];
            #pragma unroll
            for (int mi = 0; mi < 3; mi++){
                int tmi = wm*3 + mi;
                int r = tmi/6, xb = (tmi%6)*16;
                uint32_t aoff = 2u*(uint32_t)(((r+dy)*100 + xb + (lane&15) + dx)*24
                                              + (lane>>4)*8);
                ldm_x4(ah[mi], aInH + aoff);
            }
            #pragma unroll
            for (int mi = 0; mi < 3; mi++){
                #pragma unroll
                for (int j = 0; j < 2; j++){
                    MMA_F16(c[mi][j], ah[mi], &bh[j*2]);
                }
            }
        }
    }

    // ---- stage flows into smem [192 px][10] (aliases sInH) ----
    __syncthreads();
    float* sFl = reinterpret_cast<float*>(sm);
    #pragma unroll
    for (int mi = 0; mi < 3; mi++){
        int tmi = wm*3 + mi;
        int r = tmi/6, xb = (tmi%6)*16;
        int pl = r*96 + xb + (lane>>2);
        #pragma unroll
        for (int j = 0; j < 2; j++){
            int oc = wn*16 + j*8 + (lane&3)*2;
            if (oc < 10){
                float bv0 = b_fl[oc], bv1 = b_fl[oc+1];
                sFl[pl*10 + oc]         = c[mi][j][0] + bv0;
                sFl[pl*10 + oc + 1]     = c[mi][j][1] + bv1;
                sFl[(pl+8)*10 + oc]     = c[mi][j][2] + bv0;
                sFl[(pl+8)*10 + oc + 1] = c[mi][j][3] + bv1;
            }
        }
    }
    __syncthreads();

    // ---- fused warp: px-major task order (R14 layout — warp shares pixels) ----
    const __half* hb = g_inhi + (size_t)(t*Bg + b)*HW*CH + 8;
    const float scg = 96.0f/95.0f;
    for (int task = tid; task < 960; task += 256){
        int px = task/5, l = task%5;
        int y = y0 + px/96, x = px%96;
        float fx = sFl[px*10 + 2*l];
        float fy = sFl[px*10 + 2*l + 1];
        float ix = ((float)x - fx)*scg - 0.5f;
        float iy = ((float)y - fy)*scg - 0.5f;
        float fx0 = floorf(ix), fy0 = floorf(iy);
        int ix0 = (int)fx0, iy0 = (int)fy0;
        int ix1 = ix0 + 1, iy1 = iy0 + 1;
        float wx1 = ix - fx0, wy1 = iy - fy0;
        float wx0 = 1.f - wx1, wy0 = 1.f - wy1;
        float mx0 = (ix0 >= 0 && ix0 < Ww) ? 1.f : 0.f;
        float mx1 = (ix1 >= 0 && ix1 < Ww) ? 1.f : 0.f;
        float my0 = (iy0 >= 0 && iy0 < Hh) ? 1.f : 0.f;
        float my1 = (iy1 >= 0 && iy1 < Hh) ? 1.f : 0.f;
        int cx0 = min(max(ix0, 0), Ww-1), cx1 = min(max(ix1, 0), Ww-1);
        int cy0 = min(max(iy0, 0), Hh-1), cy1 = min(max(iy1, 0), Hh-1);
        float w00 = wy0*wx0*my0*mx0, w01 = wy0*wx1*my0*mx1;
        float w10 = wy1*wx0*my1*mx0, w11 = wy1*wx1*my1*mx1;
        const __half* p00 = hb + (size_t)(cy0*Ww + cx0)*CH;
        const __half* p01 = hb + (size_t)(cy0*Ww + cx1)*CH;
        const __half* p10 = hb + (size_t)(cy1*Ww + cx0)*CH;
        const __half* p11 = hb + (size_t)(cy1*Ww + cx1)*CH;
        __half* op = g_whi + ((size_t)b*HW + y*Ww + x)*KPAD + (size_t)l*Fch;
        #pragma unroll 1
        for (int cg = 0; cg < 12; cg++){
            uint4 v00 = *reinterpret_cast<const uint4*>(p00 + cg*8);
            uint4 v01 = *reinterpret_cast<const uint4*>(p01 + cg*8);
            uint4 v10 = *reinterpret_cast<const uint4*>(p10 + cg*8);
            uint4 v11 = *reinterpret_cast<const uint4*>(p11 + cg*8);
            const uint32_t* a00 = reinterpret_cast<const uint32_t*>(&v00);
            const uint32_t* a01 = reinterpret_cast<const uint32_t*>(&v01);
            const uint32_t* a10 = reinterpret_cast<const uint32_t*>(&v10);
            const uint32_t* a11 = reinterpret_cast<const uint32_t*>(&v11);
            uint32_t outw[4];
            #pragma unroll
            for (int q = 0; q < 4; q++){
                float2 f00 = __half22float2(*reinterpret_cast<const __half2*>(&a00[q]));
                float2 f01 = __half22float2(*reinterpret_cast<const __half2*>(&a01[q]));
                float2 f10 = __half22float2(*reinterpret_cast<const __half2*>(&a10[q]));
                float2 f11 = __half22float2(*reinterpret_cast<const __half2*>(&a11[q]));
                float r0 = w00*f00.x + w01*f01.x + w10*f10.x + w11*f11.x;
                float r1 = w00*f00.y + w01*f01.y + w10*f10.y + w11*f11.y;
                outw[q] = pack2(r0, r1);
            }
            *reinterpret_cast<uint4*>(op + cg*8) = *reinterpret_cast<uint4*>(outw);
        }
    }
}

// ============================================================
// prep: w_ret hi (288 x 480, stride KPAD) fp16
// ============================================================
__global__ void k_prepA(const float* __restrict__ w_ret){
    int idx = blockIdx.x*blockDim.x + threadIdx.x;
    if (idx >= FH3*KPAD) return;
    int m = idx / KPAD, k = idx % KPAD;
    float v = (k < K1) ? w_ret[m*K1 + k] : 0.f;
    g_Ahi[idx] = __float2half(v);
}

// ============================================================
// FUSED h2h GEMM (1-term fp16) + GRU gates.
// grid (72, B), 256 thr, dyn smem 66.6 KB
// ============================================================
#define TS 40
#define H2_ABUF (288*TS)
#define H2_BBUF (128*TS)
#define H2_SMEM ((2*H2_ABUF + 2*H2_BBUF)*2)   // 66560 B

__global__ void __launch_bounds__(256, 1) k_h2hg(int t,
                                                 const float* __restrict__ bias,
                                                 const float* __restrict__ hprev,
                                                 float* __restrict__ hnext,
                                                 int pack){
    extern __shared__ __half sm[];
    __half* sAh = sm;
    __half* sBh = sm + 2*H2_ABUF;
    uint32_t aSh = smem_u32(sAh), aBh = smem_u32(sBh);

    int tid = threadIdx.x, lane = tid & 31, wid = tid >> 5;
    int wm = wid & 1, wn = wid >> 1;
    int n0 = blockIdx.x*128, b = blockIdx.y;

    const __half* Bh = g_whi + ((size_t)b*HW + n0)*KPAD;

    int arow = wm*48 + (lane & 15);
    int acol = (lane >> 4) * 8;
    int brow = wn*32 + (lane & 7) + ((lane >> 4) & 1)*8;
    int bcol = ((lane >> 3) & 1) * 8;

    float c[3][3][4][4];
    #pragma unroll
    for (int mt = 0; mt < 3; mt++)
        #pragma unroll
        for (int i = 0; i < 3; i++)
            #pragma unroll
            for (int j = 0; j < 4; j++)
                #pragma unroll
                for (int q = 0; q < 4; q++) c[mt][i][j][q] = 0.f;

    #define H2G_STAGE(chunk, buf) do { \
        uint32_t sbA = (uint32_t)(buf)*(H2_ABUF*2); \
        uint32_t sbB = (uint32_t)(buf)*(H2_BBUF*2); \
        for (int e = tid; e < 1152; e += 256){ \
            int r = e >> 2, u = e & 3; \
            size_t goff = (size_t)r*KPAD + (chunk)*32 + u*8; \
            uint32_t soff = sbA + (uint32_t)(r*TS + u*8)*2u; \
            CPA16(aSh + soff, g_Ahi + goff); \
        } \
        for (int e = tid; e < 512; e += 256){ \
            int r = e >> 2, u = e & 3; \
            size_t goff = (size_t)r*KPAD + (chunk)*32 + u*8; \
            uint32_t soff = sbB + (uint32_t)(r*TS + u*8)*2u; \
            CPA16(aBh + soff, Bh + goff); \
        } \
        CPA_COMMIT(); \
    } while(0)

    H2G_STAGE(0, 0);
    for (int chunk = 0; chunk < 15; chunk++){
        if (chunk + 1 < 15){
            H2G_STAGE(chunk + 1, (chunk + 1) & 1);
            asm volatile("cp.async.wait_group 1;" ::: "memory");
        } else {
            asm volatile("cp.async.wait_group 0;" ::: "memory");
        }
        __syncthreads();

        uint32_t sbA = (uint32_t)(chunk & 1)*(H2_ABUF*2);
        uint32_t sbB = (uint32_t)(chunk & 1)*(H2_BBUF*2);
        #pragma unroll
        for (int ks = 0; ks < 2; ks++){
            int kc = ks*16;
            uint32_t bh[2][4];
            #pragma unroll
            for (int jp = 0; jp < 2; jp++){
                uint32_t off = sbB + 2u*((brow + jp*16)*TS + kc + bcol);
                ldm_x4(bh[jp], aBh + off);
            }
            #pragma unroll
            for (int mt = 0; mt < 3; mt++){
                uint32_t ah[3][4];
                #pragma unroll
                for (int mi = 0; mi < 3; mi++){
                    uint32_t off = sbA + 2u*((mt*96 + arow + mi*16)*TS + kc + acol);
                    ldm_x4(ah[mi], aSh + off);
                }
                #pragma unroll
                for (int mi = 0; mi < 3; mi++){
                    #pragma unroll
                    for (int j = 0; j < 4; j++){
                        uint32_t* fh = &bh[j >> 1][(j & 1)*2];
                        MMA_F16(c[mt][mi][j], ah[mi], fh);
                    }
                }
            }
        }
        __syncthreads();
    }

    // ---- fused GRU gate epilogue ----
    __syncthreads();
    float* sF = reinterpret_cast<float*>(sm);   // [128 px][stride 100]

    const __half* i2hb = g_i2h + (size_t)(t*Bg + b)*FH3*HW;
    const float* hpb  = hprev + (size_t)b*Fch*HW;
    float* hnb        = hnext + (size_t)b*Fch*HW;

    #pragma unroll
    for (int mi = 0; mi < 3; mi++){
        int fc0 = wm*48 + mi*16 + (lane >> 2);
        #pragma unroll
        for (int j = 0; j < 4; j++){
            int pl = wn*32 + (lane & 3)*2 + j*8;
            int p = n0 + pl;
            #pragma unroll
            for (int half_ = 0; half_ < 2; half_++){
                int fc = fc0 + half_*8;
                int q0 = half_*2;
                float rb = bias[fc], ub = bias[96 + fc], mb = bias[192 + fc];
                float2 i2r = __half22float2(*reinterpret_cast<const __half2*>(i2hb + (size_t)fc*HW + p));
                float2 i2u = __half22float2(*reinterpret_cast<const __half2*>(i2hb + (size_t)(96+fc)*HW + p));
                float2 i2m = __half22float2(*reinterpret_cast<const __half2*>(i2hb + (size_t)(192+fc)*HW + p));
                float2 hpv = *reinterpret_cast<const float2*>(hpb + (size_t)fc*HW + p);
                float nh[2];
                #pragma unroll
                for (int s = 0; s < 2; s++){
                    float hr = c[0][mi][j][q0+s] + rb;
                    float hu = c[1][mi][j][q0+s] + ub;
                    float hm = c[2][mi][j][q0+s] + mb;
                    float ir = s ? i2r.y : i2r.x;
                    float iu = s ? i2u.y : i2u.x;
                    float im = s ? i2m.y : i2m.x;
                    float hp = s ? hpv.y : hpv.x;
                    float reset  = sigm(ir + hr);
                    float update = sigm(iu + hu);
                    float newmem = leaky(im + reset*hm);
                    nh[s] = update*hp + (1.f - update)*newmem;
                }
                float2 wv; wv.x = nh[0]; wv.y = nh[1];
                *reinterpret_cast<float2*>(hnb + (size_t)fc*HW + p) = wv;
                sF[pl*100 + fc]     = nh[0];
                sF[(pl+1)*100 + fc] = nh[1];
            }
        }
    }
    __syncthreads();
    if (pack){
        size_t slotn = (size_t)((t+1)*Bg + b)*HW;
        for (int e = tid; e < 128*12; e += 256){
            int pl = e/12, u = e%12;
            const float* src = sF + pl*100 + u*8;
            uint32_t hw[4];
            #pragma unroll
            for (int q = 0; q < 4; q++)
                hw[q] = pack2(src[2*q], src[2*q+1]);
            size_t off = (slotn + n0 + pl)*CH + 8 + u*8;
            *reinterpret_cast<uint4*>(g_inhi + off) = *reinterpret_cast<uint4*>(hw);
        }
    }
}

// ============================================================
extern "C" void kernel_launch(void* const* d_in, const int* in_sizes, int n_in,
                              void* d_out, int out_size){
    const float* inputs = (const float*)d_in[0];
    const float* h0     = (const float*)d_in[1];
    const float* w_i2h  = (const float*)d_in[2];
    const float* b_i2h  = (const float*)d_in[3];
    const float* w_i2f  = (const float*)d_in[4];
    const float* b_i2f  = (const float*)d_in[5];
    const float* w_h2f  = (const float*)d_in[6];
    const float* b_h2f  = (const float*)d_in[7];
    const float* w_fl   = (const float*)d_in[8];
    const float* b_fl   = (const float*)d_in[9];
    const float* w_ret  = (const float*)d_in[10];
    const float* b_ret  = (const float*)d_in[11];
    float* out = (float*)d_out;

    static cudaStream_t s2 = nullptr;
    static cudaEvent_t evRoot = nullptr;
    static cudaEvent_t evI[Sg];
    if (!s2){
        cudaStreamCreateWithFlags(&s2, cudaStreamNonBlocking);
        cudaEventCreateWithFlags(&evRoot, cudaEventDisableTiming);
        for (int t = 0; t < Sg; t++)
            cudaEventCreateWithFlags(&evI[t], cudaEventDisableTiming);
        cudaFuncSetAttribute(k_fconv,  cudaFuncAttributeMaxDynamicSharedMemorySize, FSM_BYTES);
        cudaFuncSetAttribute(k_flowsW, cudaFuncAttributeMaxDynamicSharedMemorySize, FSM_BYTES);
        cudaFuncSetAttribute(k_h2hg,   cudaFuncAttributeMaxDynamicSharedMemorySize, H2_SMEM);
    }

    k_prepX   <<<(Sg*Bg*HW + 255)/256, 256>>>(inputs, h0);
    k_prepWall<<<(89600 + 25600 + 20736 + 255)/256, 256>>>(w_i2f, w_h2f, w_fl, w_i2h);
    k_prepA   <<<(FH3*KPAD + 255)/256, 256>>>(w_ret);

    cudaEventRecord(evRoot, 0);
    cudaStreamWaitEvent(s2, evRoot, 0);
    for (int t = 0; t < Sg; t++){
        k_i2hT<<<dim3(48, 2), 256, 0, s2>>>(t*Bg, b_i2h);
        cudaEventRecord(evI[t], s2);
    }

    for (int t = 0; t < Sg; t++){
        const float* h = (t == 0) ? h0 : out + (size_t)(t-1)*STEP_ELEMS;
        float* hn = out + (size_t)t*STEP_ELEMS;

        k_fconv <<<dim3(48, Bg), 256, FSM_BYTES>>>(t, b_i2f, b_h2f);
        k_flowsW<<<dim3(48, Bg), 256, FSM_BYTES>>>(t, b_fl);
        cudaStreamWaitEvent(0, evI[t], 0);
        k_h2hg  <<<dim3(HW/128, Bg), 256, H2_SMEM>>>(t, b_ret, h, hn, (t < Sg-1) ? 1 : 0);
    }

    const size_t OUT_SEQ = (size_t)Sg*STEP_ELEMS;
    if ((size_t)out_size >= OUT_SEQ + STEP_ELEMS){
        cudaMemcpyAsync(out + OUT_SEQ, out + (size_t)(Sg-1)*STEP_ELEMS,
                        (size_t)STEP_ELEMS*sizeof(float),
                        cudaMemcpyDeviceToDevice);
    }
}